// round 2
// baseline (speedup 1.0000x reference)
#include <cuda_runtime.h>
#include <cuda_bf16.h>
#include <cstdint>

// ---------------- scratch (static __device__, no allocation) ----------------
__device__ float g_conv[8192 * 256];    // conv_all  [B*S, 256]
__device__ float g_x[8192 * 256];       // layer input/output [B*S, 256]
__device__ float g_gates[8192 * 768];   // xg for one layer, both dirs [B*S, 768]

// ---------------- constants ----------------
#define Bsz 128
#define Ssz 64
#define Psz 32
#define Dsz 256
#define Hsz 128

// packed f32x2 FMA: d = a*b + d (element-wise fp32, RN) — Blackwell FFMA2
#define FMA2(acc, a, b) \
    asm("fma.rn.f32x2 %0, %1, %2, %0;" : "+l"(acc) : "l"(a), "l"(b))

__device__ __forceinline__ float pk_lo(unsigned long long p) {
    return __uint_as_float((unsigned)(p & 0xffffffffull));
}
__device__ __forceinline__ float pk_hi(unsigned long long p) {
    return __uint_as_float((unsigned)(p >> 32));
}

// fast transcendentals (MUFU.EX2/RCP based; ~1e-7 rel err)
__device__ __forceinline__ float fsig(float x) {
    float e = __expf(-x);
    return __fdividef(1.0f, 1.0f + e);
}
__device__ __forceinline__ float ftanh(float x) {
    float ax = fabsf(x);
    float e = __expf(-2.0f * ax);
    float r = __fdividef(1.0f - e, 1.0f + e);
    return copysignf(r, x);
}

// =====================================================================
// Kernel 1: fused conv scalar + weighted event sum (HBM streaming bound)
// =====================================================================
__global__ __launch_bounds__(256)
void conv_kernel(const float* __restrict__ in, const float* __restrict__ conv_w,
                 const float* __restrict__ conv_b, float* __restrict__ out)
{
    __shared__ __align__(16) float tile[Psz * Dsz];   // 32 KB
    __shared__ float cw[Dsz];
    __shared__ float sp[Psz];

    const int tid = threadIdx.x;
    const float* src = in + (size_t)blockIdx.x * (Psz * Dsz);

    cw[tid] = conv_w[tid];
    const float4* src4 = (const float4*)src;
    float4* tile4 = (float4*)tile;
#pragma unroll
    for (int i = 0; i < 8; i++)
        tile4[tid + i * 256] = src4[tid + i * 256];
    __syncthreads();

    const int warp = tid >> 5, lane = tid & 31;
#pragma unroll
    for (int r = 0; r < 4; r++) {
        int p = warp * 4 + r;
        float acc = 0.f;
#pragma unroll
        for (int j = 0; j < 8; j++)
            acc += tile[p * Dsz + lane + j * 32] * cw[lane + j * 32];
#pragma unroll
        for (int o = 16; o; o >>= 1)
            acc += __shfl_xor_sync(0xffffffffu, acc, o);
        if (lane == 0) sp[p] = acc + conv_b[0];
    }
    __syncthreads();

    float acc = 0.f;
#pragma unroll
    for (int p = 0; p < Psz; p++)
        acc += sp[p] * tile[p * Dsz + tid];
    out[(size_t)blockIdx.x * Dsz + tid] = acc;
}

// =====================================================================
// Kernel 2: SGEMM with packed FFMA2.  C[m,n] = sum_k A[m,k]*B[n,k]
// BM=128 BN=64 BK=16, 256 threads, each thread: 8 m (4 packed pairs) x 4 n.
// B is duplicated in SMEM as (b,b) pairs so no pack instructions needed.
// =====================================================================
#define BM 128
#define BN 64
#define BK 16
#define AS_LD (BM + 4)       // 132 floats / row  (528 B, 16B-multiple)
#define BS_LD (2 * BN + 8)   // 136 floats / row  (544 B, 16B-multiple)

template<bool CLIP, bool BIAS>
__global__ __launch_bounds__(256)
void sgemm_nt(const float* __restrict__ A, const float* __restrict__ B,
              const float* __restrict__ bias, float* __restrict__ C,
              int M, int N, int K)
{
    __shared__ __align__(16) float As[BK][AS_LD];
    __shared__ __align__(16) float Bs[BK][BS_LD];   // duplicated pairs

    const int tid = threadIdx.x;
    const int bm = blockIdx.y * BM;
    const int bn = blockIdx.x * BN;

    const int lrow = tid >> 2;           // 0..63
    const int lk   = (tid & 3) * 4;      // 0,4,8,12

    const int tx = tid & 15;             // n-tile (4 cols)
    const int ty = tid >> 4;             // m-tile (8 rows = 4 pairs)

    unsigned long long acc[4][4];
#pragma unroll
    for (int p = 0; p < 4; p++)
#pragma unroll
        for (int j = 0; j < 4; j++) acc[p][j] = 0ull;

    const unsigned aAddr = (unsigned)__cvta_generic_to_shared(&As[0][ty * 8]);
    const unsigned bAddr = (unsigned)__cvta_generic_to_shared(&Bs[0][tx * 8]);

    for (int kt = 0; kt < K; kt += BK) {
        float4 a0 = *(const float4*)&A[(size_t)(bm + lrow) * K + kt + lk];
        float4 a1 = *(const float4*)&A[(size_t)(bm + lrow + 64) * K + kt + lk];
        float4 b0 = *(const float4*)&B[(size_t)(bn + lrow) * K + kt + lk];
        __syncthreads();
        As[lk + 0][lrow] = a0.x; As[lk + 1][lrow] = a0.y;
        As[lk + 2][lrow] = a0.z; As[lk + 3][lrow] = a0.w;
        As[lk + 0][lrow + 64] = a1.x; As[lk + 1][lrow + 64] = a1.y;
        As[lk + 2][lrow + 64] = a1.z; As[lk + 3][lrow + 64] = a1.w;
        *(float2*)&Bs[lk + 0][2 * lrow] = make_float2(b0.x, b0.x);
        *(float2*)&Bs[lk + 1][2 * lrow] = make_float2(b0.y, b0.y);
        *(float2*)&Bs[lk + 2][2 * lrow] = make_float2(b0.z, b0.z);
        *(float2*)&Bs[lk + 3][2 * lrow] = make_float2(b0.w, b0.w);
        __syncthreads();

#pragma unroll
        for (int k = 0; k < BK; k++) {
            unsigned long long ap0, ap1, ap2, ap3, bb0, bb1, bb2, bb3;
            asm volatile("ld.shared.v2.b64 {%0,%1},[%2];"
                         : "=l"(ap0), "=l"(ap1) : "r"(aAddr + k * (AS_LD * 4)));
            asm volatile("ld.shared.v2.b64 {%0,%1},[%2];"
                         : "=l"(ap2), "=l"(ap3) : "r"(aAddr + k * (AS_LD * 4) + 16));
            asm volatile("ld.shared.v2.b64 {%0,%1},[%2];"
                         : "=l"(bb0), "=l"(bb1) : "r"(bAddr + k * (BS_LD * 4)));
            asm volatile("ld.shared.v2.b64 {%0,%1},[%2];"
                         : "=l"(bb2), "=l"(bb3) : "r"(bAddr + k * (BS_LD * 4) + 16));
            FMA2(acc[0][0], ap0, bb0); FMA2(acc[0][1], ap0, bb1);
            FMA2(acc[0][2], ap0, bb2); FMA2(acc[0][3], ap0, bb3);
            FMA2(acc[1][0], ap1, bb0); FMA2(acc[1][1], ap1, bb1);
            FMA2(acc[1][2], ap1, bb2); FMA2(acc[1][3], ap1, bb3);
            FMA2(acc[2][0], ap2, bb0); FMA2(acc[2][1], ap2, bb1);
            FMA2(acc[2][2], ap2, bb2); FMA2(acc[2][3], ap2, bb3);
            FMA2(acc[3][0], ap3, bb0); FMA2(acc[3][1], ap3, bb1);
            FMA2(acc[3][2], ap3, bb2); FMA2(acc[3][3], ap3, bb3);
        }
    }

    float bset[4] = {0.f, 0.f, 0.f, 0.f};
    if (BIAS) {
#pragma unroll
        for (int j = 0; j < 4; j++) bset[j] = bias[bn + tx * 4 + j];
    }
#pragma unroll
    for (int p = 0; p < 4; p++) {
        float4 vlo, vhi;
        float* lp = (float*)&vlo;
        float* hp = (float*)&vhi;
#pragma unroll
        for (int j = 0; j < 4; j++) {
            float tl = pk_lo(acc[p][j]) + bset[j];
            float th = pk_hi(acc[p][j]) + bset[j];
            if (CLIP) {
                tl = fminf(1.0f, fmaxf(-1.0f, tl));
                th = fminf(1.0f, fmaxf(-1.0f, th));
            }
            lp[j] = tl; hp[j] = th;
        }
        int row = bm + ty * 8 + 2 * p;
        *(float4*)&C[(size_t)row * N + bn + tx * 4]       = vlo;
        *(float4*)&C[(size_t)(row + 1) * N + bn + tx * 4] = vhi;
    }
}

// =====================================================================
// Kernel 3: GRU scan, packed-FFMA2 matvec.
// 128 blocks (dir x batch-pair), 384 threads. Thread g holds Whh row g
// as 64 packed (w_k, w_{k+1}) b64 registers; h in SMEM, loaded as b64
// pairs. Per step/thread: 128 fma2 + 64 LDS.128 (FMA-pipe bound).
// =====================================================================
__global__ __launch_bounds__(384, 1)
void gru_scan(const float* __restrict__ gates, const float* __restrict__ Whh,
              const float* __restrict__ bhh, float* __restrict__ out)
{
    const int dir = blockIdx.x >> 6;
    const int bpair = blockIdx.x & 63;
    const int b0 = bpair * 2;
    const int g = threadIdx.x;

    // register-resident packed weight row (128 floats -> 64 b64 pairs)
    const ulonglong2* W2 = (const ulonglong2*)(Whh + (size_t)dir * 384 * 128
                                               + (size_t)g * 128);
    unsigned long long w[64];
#pragma unroll
    for (int i = 0; i < 32; i++) {
        ulonglong2 t = W2[i];
        w[2 * i] = t.x; w[2 * i + 1] = t.y;
    }
    const float bias = bhh[dir * 384 + g];

    __shared__ __align__(16) float h0[Hsz];
    __shared__ __align__(16) float h1[Hsz];
    __shared__ float gh0[384];
    __shared__ float gh1[384];

    if (g < Hsz) { h0[g] = 0.f; h1[g] = 0.f; }
    __syncthreads();

    const unsigned h0a = (unsigned)__cvta_generic_to_shared(h0);
    const unsigned h1a = (unsigned)__cvta_generic_to_shared(h1);

    const int j = g & 127;
    const int isb1 = (g >= 128 && g < 256) ? 1 : 0;
    const int bc = b0 + isb1;

    for (int t_ = 0; t_ < Ssz; t_++) {
        const int t = dir ? (Ssz - 1 - t_) : t_;

        // early-issue xg loads (hidden behind the matvec)
        float xr = 0.f, xz = 0.f, xn = 0.f;
        if (g < 256) {
            const float* gb = gates + ((size_t)(bc * Ssz + t)) * 768 + dir * 384;
            xr = gb[j];
            xz = gb[128 + j];
            xn = gb[256 + j];
        }

        unsigned long long acc0 = 0ull, acc1 = 0ull;
#pragma unroll
        for (int i = 0; i < 32; i++) {
            unsigned long long p0, p1, q0, q1;
            asm volatile("ld.shared.v2.b64 {%0,%1},[%2];"
                         : "=l"(p0), "=l"(p1) : "r"(h0a + i * 16));
            asm volatile("ld.shared.v2.b64 {%0,%1},[%2];"
                         : "=l"(q0), "=l"(q1) : "r"(h1a + i * 16));
            FMA2(acc0, w[2 * i], p0);
            FMA2(acc0, w[2 * i + 1], p1);
            FMA2(acc1, w[2 * i], q0);
            FMA2(acc1, w[2 * i + 1], q1);
        }
        gh0[g] = pk_lo(acc0) + pk_hi(acc0) + bias;
        gh1[g] = pk_lo(acc1) + pk_hi(acc1) + bias;
        __syncthreads();

        if (g < 256) {
            float* h  = isb1 ? h1 : h0;
            float* gh = isb1 ? gh1 : gh0;
            float r = fsig(xr + gh[j]);
            float z = fsig(xz + gh[128 + j]);
            float n = ftanh(xn + r * gh[256 + j]);
            float hnew = n + z * (h[j] - n);   // (1-z)*n + z*h
            h[j] = hnew;
            out[((size_t)(bc * Ssz + t)) * 256 + dir * 128 + j] = hnew;
        }
        __syncthreads();
    }
}

// =====================================================================
// Kernel 4: epilogue. alpha == 1 exactly (softmax over singleton axis).
// =====================================================================
__global__ __launch_bounds__(256)
void epilogue_kernel(const float* __restrict__ states, const float* __restrict__ lin_w,
                     const float* __restrict__ lin_b, float* __restrict__ out_out,
                     float* __restrict__ out_ctx, float* __restrict__ out_alpha)
{
    __shared__ float ctx[256];
    __shared__ float logits[2];
    const int b = blockIdx.x;
    const int tid = threadIdx.x;

    const float* sb = states + (size_t)b * Ssz * 256;
    float acc = 0.f;
#pragma unroll
    for (int s = 0; s < Ssz; s++)
        acc += sb[s * 256 + tid];
    ctx[tid] = acc;
    out_ctx[(size_t)b * 256 + tid] = acc;
    if (tid < Ssz) out_alpha[(size_t)b * Ssz + tid] = 1.0f;
    __syncthreads();

    if (tid < 64) {
        const int o = tid >> 5, lane = tid & 31;
        float p = 0.f;
#pragma unroll
        for (int k = 0; k < 8; k++)
            p += ctx[lane + k * 32] * lin_w[o * 256 + lane + k * 32];
#pragma unroll
        for (int off = 16; off; off >>= 1)
            p += __shfl_xor_sync(0xffffffffu, p, off);
        if (lane == 0) logits[o] = p + lin_b[o];
    }
    __syncthreads();
    if (tid == 0) {
        float l0 = logits[0], l1 = logits[1];
        float m = fmaxf(l0, l1);
        float e0 = expf(l0 - m), e1 = expf(l1 - m);
        float inv = 1.0f / (e0 + e1);
        out_out[b * 2 + 0] = e0 * inv;
        out_out[b * 2 + 1] = e1 * inv;
    }
}

// =====================================================================
// launcher
// =====================================================================
extern "C" void kernel_launch(void* const* d_in, const int* in_sizes, int n_in,
                              void* d_out, int out_size)
{
    const float* inputs  = (const float*)d_in[0];   // [128,64,32,256]
    const float* conv_w  = (const float*)d_in[1];   // [256]
    const float* conv_b  = (const float*)d_in[2];   // [1]
    const float* embed_w = (const float*)d_in[3];   // [256,256]
    const float* Wih     = (const float*)d_in[4];   // [2,2,384,256]
    const float* Whh     = (const float*)d_in[5];   // [2,2,384,128]
    const float* bih     = (const float*)d_in[6];   // [2,2,384]
    const float* bhh     = (const float*)d_in[7];   // [2,2,384]
    // d_in[8] = att_w1: mathematically unused (A==1 -> softmax == 1)
    const float* lin_w   = (const float*)d_in[9];   // [2,256]
    const float* lin_b   = (const float*)d_in[10];  // [2]

    float* out_base = (float*)d_out;
    const int total_expected = 256 + 8192 * 256 + 128 * 256 + 128 * 64;
    float* out_out    = out_base;
    float* out_states = out_base + 256;
    float* out_ctx    = out_states + 8192 * 256;
    float* out_alpha  = out_ctx + 128 * 256;
    const bool full = (out_size >= total_expected);

    float *pconv, *px, *pgates;
    cudaGetSymbolAddress((void**)&pconv, g_conv);
    cudaGetSymbolAddress((void**)&px, g_x);
    cudaGetSymbolAddress((void**)&pgates, g_gates);

    // 1) fused conv + weighted sum -> g_conv [8192,256]
    conv_kernel<<<Bsz * Ssz, 256>>>(inputs, conv_w, conv_b, pconv);

    // 2) embed + hardtanh -> g_x [8192,256]
    sgemm_nt<true, false><<<dim3(256 / BN, 8192 / BM), 256>>>(
        pconv, embed_w, nullptr, px, 8192, 256, 256);

    // 3) two bidirectional GRU layers
    for (int l = 0; l < 2; l++) {
        const float* WihL = Wih + (size_t)l * 2 * 384 * 256;
        const float* bihL = bih + (size_t)l * 2 * 384;
        const float* WhhL = Whh + (size_t)l * 2 * 384 * 128;
        const float* bhhL = bhh + (size_t)l * 2 * 384;

        sgemm_nt<false, true><<<dim3(768 / BN, 8192 / BM), 256>>>(
            px, WihL, bihL, pgates, 8192, 768, 256);

        float* dst = (l == 0) ? px : (full ? out_states : px);
        gru_scan<<<128, 384>>>(pgates, WhhL, bhhL, dst);
    }

    // 4) epilogue: context / alpha / output softmax
    const float* states_src = full ? out_states : px;
    if (full) {
        epilogue_kernel<<<Bsz, 256>>>(states_src, lin_w, lin_b,
                                      out_out, out_ctx, out_alpha);
    } else {
        epilogue_kernel<<<Bsz, 256>>>(states_src, lin_w, lin_b,
                                      out_out, pconv, pconv + 128 * 256);
    }
}

// round 3
// speedup vs baseline: 1.0254x; 1.0254x over previous
#include <cuda_runtime.h>
#include <cuda_bf16.h>
#include <cstdint>

// ---------------- scratch (static __device__, no allocation) ----------------
__device__ float g_conv[8192 * 256];    // conv_all  [B*S, 256]
__device__ float g_x[8192 * 256];       // layer input/output [B*S, 256]
__device__ float g_gates[8192 * 768];   // xg for one layer, both dirs [B*S, 768]

// ---------------- constants ----------------
#define Bsz 128
#define Ssz 64
#define Psz 32
#define Dsz 256
#define Hsz 128

// packed f32x2 FMA: d = a*b + d (element-wise fp32, RN). NON-volatile:
// compiler/ptxas may reorder freely; operands arrive as b64 register pairs
// directly from LDS.128 (no pack MOVs).
#define FMA2(acc, a, b) \
    asm("fma.rn.f32x2 %0, %1, %2, %0;" : "+l"(acc) : "l"(a), "l"(b))

__device__ __forceinline__ float pk_lo(unsigned long long p) {
    return __uint_as_float((unsigned)(p & 0xffffffffull));
}
__device__ __forceinline__ float pk_hi(unsigned long long p) {
    return __uint_as_float((unsigned)(p >> 32));
}

// fast transcendentals (MUFU based; ~1e-7 rel err)
__device__ __forceinline__ float fsig(float x) {
    float e = __expf(-x);
    return __fdividef(1.0f, 1.0f + e);
}
__device__ __forceinline__ float ftanh(float x) {
    float ax = fabsf(x);
    float e = __expf(-2.0f * ax);
    float r = __fdividef(1.0f - e, 1.0f + e);
    return copysignf(r, x);
}

// =====================================================================
// Kernel 1: fused conv scalar + weighted event sum (HBM streaming bound)
// =====================================================================
__global__ __launch_bounds__(256)
void conv_kernel(const float* __restrict__ in, const float* __restrict__ conv_w,
                 const float* __restrict__ conv_b, float* __restrict__ out)
{
    __shared__ __align__(16) float tile[Psz * Dsz];   // 32 KB
    __shared__ float cw[Dsz];
    __shared__ float sp[Psz];

    const int tid = threadIdx.x;
    const float* src = in + (size_t)blockIdx.x * (Psz * Dsz);

    cw[tid] = conv_w[tid];
    const float4* src4 = (const float4*)src;
    float4* tile4 = (float4*)tile;
#pragma unroll
    for (int i = 0; i < 8; i++)
        tile4[tid + i * 256] = src4[tid + i * 256];
    __syncthreads();

    const int warp = tid >> 5, lane = tid & 31;
#pragma unroll
    for (int r = 0; r < 4; r++) {
        int p = warp * 4 + r;
        float acc = 0.f;
#pragma unroll
        for (int j = 0; j < 8; j++)
            acc += tile[p * Dsz + lane + j * 32] * cw[lane + j * 32];
#pragma unroll
        for (int o = 16; o; o >>= 1)
            acc += __shfl_xor_sync(0xffffffffu, acc, o);
        if (lane == 0) sp[p] = acc + conv_b[0];
    }
    __syncthreads();

    float acc = 0.f;
#pragma unroll
    for (int p = 0; p < Psz; p++)
        acc += sp[p] * tile[p * Dsz + tid];
    out[(size_t)blockIdx.x * Dsz + tid] = acc;
}

// =====================================================================
// Kernel 2: SGEMM, packed FFMA2 with pure C++ SMEM loads.
//   C[m,n] = sum_k A[m,k]*B[n,k] (+bias[n]) (clip)
// BM=128 BN=64 BK=16, 256 thr. Thread tile: 8 m (4 b64 pairs) x 4 n.
// A tile stored as [k][m] (m-pairs contiguous -> b64 pairs free).
// B tile stored duplicated (b,b) so b64 broadcast operands are free.
// Per k-iter: 4x LDS.128 + 16x FFMA2.
// =====================================================================
#define BM 128
#define BN 64
#define BK 16
#define AS_LD (BM + 4)       // 132 floats/row
#define BS_LD (2 * BN + 8)   // 136 floats/row (duplicated pairs)

template<bool CLIP, bool BIAS>
__global__ __launch_bounds__(256)
void sgemm_nt(const float* __restrict__ A, const float* __restrict__ B,
              const float* __restrict__ bias, float* __restrict__ C,
              int M, int N, int K)
{
    __shared__ __align__(16) float As[BK][AS_LD];
    __shared__ __align__(16) float Bs[BK][BS_LD];

    const int tid = threadIdx.x;
    const int bm = blockIdx.y * BM;
    const int bn = blockIdx.x * BN;

    const int lrow = tid >> 2;           // 0..63
    const int lk   = (tid & 3) * 4;      // 0,4,8,12

    const int tx = tid & 15;             // n-tile (4 cols)
    const int ty = tid >> 4;             // m-tile (8 rows = 4 pairs)

    unsigned long long acc[4][4];
#pragma unroll
    for (int p = 0; p < 4; p++)
#pragma unroll
        for (int j = 0; j < 4; j++) acc[p][j] = 0ull;

    for (int kt = 0; kt < K; kt += BK) {
        float4 a0 = *(const float4*)&A[(size_t)(bm + lrow) * K + kt + lk];
        float4 a1 = *(const float4*)&A[(size_t)(bm + lrow + 64) * K + kt + lk];
        float4 b0 = *(const float4*)&B[(size_t)(bn + lrow) * K + kt + lk];
        __syncthreads();
        As[lk + 0][lrow] = a0.x; As[lk + 1][lrow] = a0.y;
        As[lk + 2][lrow] = a0.z; As[lk + 3][lrow] = a0.w;
        As[lk + 0][lrow + 64] = a1.x; As[lk + 1][lrow + 64] = a1.y;
        As[lk + 2][lrow + 64] = a1.z; As[lk + 3][lrow + 64] = a1.w;
        *(float2*)&Bs[lk + 0][2 * lrow] = make_float2(b0.x, b0.x);
        *(float2*)&Bs[lk + 1][2 * lrow] = make_float2(b0.y, b0.y);
        *(float2*)&Bs[lk + 2][2 * lrow] = make_float2(b0.z, b0.z);
        *(float2*)&Bs[lk + 3][2 * lrow] = make_float2(b0.w, b0.w);
        __syncthreads();

#pragma unroll
        for (int k = 0; k < BK; k++) {
            ulonglong2 apl = *(const ulonglong2*)&As[k][ty * 8];      // (m0,m1),(m2,m3)
            ulonglong2 aph = *(const ulonglong2*)&As[k][ty * 8 + 4];  // (m4,m5),(m6,m7)
            ulonglong2 bbl = *(const ulonglong2*)&Bs[k][tx * 8];      // (n0,n0),(n1,n1)
            ulonglong2 bbh = *(const ulonglong2*)&Bs[k][tx * 8 + 4];  // (n2,n2),(n3,n3)
            FMA2(acc[0][0], apl.x, bbl.x); FMA2(acc[0][1], apl.x, bbl.y);
            FMA2(acc[0][2], apl.x, bbh.x); FMA2(acc[0][3], apl.x, bbh.y);
            FMA2(acc[1][0], apl.y, bbl.x); FMA2(acc[1][1], apl.y, bbl.y);
            FMA2(acc[1][2], apl.y, bbh.x); FMA2(acc[1][3], apl.y, bbh.y);
            FMA2(acc[2][0], aph.x, bbl.x); FMA2(acc[2][1], aph.x, bbl.y);
            FMA2(acc[2][2], aph.x, bbh.x); FMA2(acc[2][3], aph.x, bbh.y);
            FMA2(acc[3][0], aph.y, bbl.x); FMA2(acc[3][1], aph.y, bbl.y);
            FMA2(acc[3][2], aph.y, bbh.x); FMA2(acc[3][3], aph.y, bbh.y);
        }
    }

    float bset[4] = {0.f, 0.f, 0.f, 0.f};
    if (BIAS) {
#pragma unroll
        for (int j = 0; j < 4; j++) bset[j] = bias[bn + tx * 4 + j];
    }
#pragma unroll
    for (int p = 0; p < 4; p++) {
        float4 vlo, vhi;
        float* lp = (float*)&vlo;
        float* hp = (float*)&vhi;
#pragma unroll
        for (int j = 0; j < 4; j++) {
            float tl = pk_lo(acc[p][j]) + bset[j];
            float th = pk_hi(acc[p][j]) + bset[j];
            if (CLIP) {
                tl = fminf(1.0f, fmaxf(-1.0f, tl));
                th = fminf(1.0f, fmaxf(-1.0f, th));
            }
            lp[j] = tl; hp[j] = th;
        }
        int row = bm + ty * 8 + 2 * p;
        *(float4*)&C[(size_t)row * N + bn + tx * 4]       = vlo;
        *(float4*)&C[(size_t)(row + 1) * N + bn + tx * 4] = vhi;
    }
}

// =====================================================================
// Kernel 3: GRU scan, FFMA2 matvec, pure C++ ulonglong2 SMEM loads.
// 128 blocks (dir x batch-pair), 384 threads, Whh row in registers.
// =====================================================================
__global__ __launch_bounds__(384, 1)
void gru_scan(const float* __restrict__ gates, const float* __restrict__ Whh,
              const float* __restrict__ bhh, float* __restrict__ out)
{
    const int dir = blockIdx.x >> 6;
    const int bpair = blockIdx.x & 63;
    const int b0 = bpair * 2;
    const int g = threadIdx.x;

    // register-resident packed weight row (128 floats -> 64 b64 pairs)
    const ulonglong2* W2 = (const ulonglong2*)(Whh + (size_t)dir * 384 * 128
                                               + (size_t)g * 128);
    unsigned long long w[64];
#pragma unroll
    for (int i = 0; i < 32; i++) {
        ulonglong2 t = W2[i];
        w[2 * i] = t.x; w[2 * i + 1] = t.y;
    }
    const float bias = bhh[dir * 384 + g];

    __shared__ __align__(16) float h0[Hsz];
    __shared__ __align__(16) float h1[Hsz];
    __shared__ float gh0[384];
    __shared__ float gh1[384];

    if (g < Hsz) { h0[g] = 0.f; h1[g] = 0.f; }
    __syncthreads();

    const int j = g & 127;
    const int isb1 = (g >= 128 && g < 256) ? 1 : 0;
    const int bc = b0 + isb1;

    const ulonglong2* h0v = (const ulonglong2*)h0;   // 16 x (2 b64) = 128 floats
    const ulonglong2* h1v = (const ulonglong2*)h1;

    for (int t_ = 0; t_ < Ssz; t_++) {
        const int t = dir ? (Ssz - 1 - t_) : t_;

        // early-issue xg loads (hidden behind the matvec)
        float xr = 0.f, xz = 0.f, xn = 0.f;
        if (g < 256) {
            const float* gb = gates + ((size_t)(bc * Ssz + t)) * 768 + dir * 384;
            xr = gb[j];
            xz = gb[128 + j];
            xn = gb[256 + j];
        }

        unsigned long long acc0 = 0ull, acc1 = 0ull;
#pragma unroll
        for (int i = 0; i < 16; i++) {
            ulonglong2 p = h0v[i];    // floats 4i..4i+3, batch 0
            ulonglong2 q = h1v[i];    // floats 4i..4i+3, batch 1
            FMA2(acc0, w[2 * i],     p.x);
            FMA2(acc0, w[2 * i + 1], p.y);
            FMA2(acc1, w[2 * i],     q.x);
            FMA2(acc1, w[2 * i + 1], q.y);
        }
#pragma unroll
        for (int i = 16; i < 32; i++) {
            ulonglong2 p = h0v[i];
            ulonglong2 q = h1v[i];
            FMA2(acc0, w[2 * i],     p.x);
            FMA2(acc0, w[2 * i + 1], p.y);
            FMA2(acc1, w[2 * i],     q.x);
            FMA2(acc1, w[2 * i + 1], q.y);
        }
        gh0[g] = pk_lo(acc0) + pk_hi(acc0) + bias;
        gh1[g] = pk_lo(acc1) + pk_hi(acc1) + bias;
        __syncthreads();

        if (g < 256) {
            float* h  = isb1 ? h1 : h0;
            float* gh = isb1 ? gh1 : gh0;
            float r = fsig(xr + gh[j]);
            float z = fsig(xz + gh[128 + j]);
            float n = ftanh(xn + r * gh[256 + j]);
            float hnew = n + z * (h[j] - n);   // (1-z)*n + z*h
            h[j] = hnew;
            out[((size_t)(bc * Ssz + t)) * 256 + dir * 128 + j] = hnew;
        }
        __syncthreads();
    }
}

// =====================================================================
// Kernel 4: epilogue. alpha == 1 exactly (softmax over singleton axis).
// =====================================================================
__global__ __launch_bounds__(256)
void epilogue_kernel(const float* __restrict__ states, const float* __restrict__ lin_w,
                     const float* __restrict__ lin_b, float* __restrict__ out_out,
                     float* __restrict__ out_ctx, float* __restrict__ out_alpha)
{
    __shared__ float ctx[256];
    __shared__ float logits[2];
    const int b = blockIdx.x;
    const int tid = threadIdx.x;

    const float* sb = states + (size_t)b * Ssz * 256;
    float acc = 0.f;
#pragma unroll
    for (int s = 0; s < Ssz; s++)
        acc += sb[s * 256 + tid];
    ctx[tid] = acc;
    out_ctx[(size_t)b * 256 + tid] = acc;
    if (tid < Ssz) out_alpha[(size_t)b * Ssz + tid] = 1.0f;
    __syncthreads();

    if (tid < 64) {
        const int o = tid >> 5, lane = tid & 31;
        float p = 0.f;
#pragma unroll
        for (int k = 0; k < 8; k++)
            p += ctx[lane + k * 32] * lin_w[o * 256 + lane + k * 32];
#pragma unroll
        for (int off = 16; off; off >>= 1)
            p += __shfl_xor_sync(0xffffffffu, p, off);
        if (lane == 0) logits[o] = p + lin_b[o];
    }
    __syncthreads();
    if (tid == 0) {
        float l0 = logits[0], l1 = logits[1];
        float m = fmaxf(l0, l1);
        float e0 = expf(l0 - m), e1 = expf(l1 - m);
        float inv = 1.0f / (e0 + e1);
        out_out[b * 2 + 0] = e0 * inv;
        out_out[b * 2 + 1] = e1 * inv;
    }
}

// =====================================================================
// launcher
// =====================================================================
extern "C" void kernel_launch(void* const* d_in, const int* in_sizes, int n_in,
                              void* d_out, int out_size)
{
    const float* inputs  = (const float*)d_in[0];   // [128,64,32,256]
    const float* conv_w  = (const float*)d_in[1];   // [256]
    const float* conv_b  = (const float*)d_in[2];   // [1]
    const float* embed_w = (const float*)d_in[3];   // [256,256]
    const float* Wih     = (const float*)d_in[4];   // [2,2,384,256]
    const float* Whh     = (const float*)d_in[5];   // [2,2,384,128]
    const float* bih     = (const float*)d_in[6];   // [2,2,384]
    const float* bhh     = (const float*)d_in[7];   // [2,2,384]
    // d_in[8] = att_w1: mathematically unused (A==1 -> softmax == 1)
    const float* lin_w   = (const float*)d_in[9];   // [2,256]
    const float* lin_b   = (const float*)d_in[10];  // [2]

    float* out_base = (float*)d_out;
    const int total_expected = 256 + 8192 * 256 + 128 * 256 + 128 * 64;
    float* out_out    = out_base;
    float* out_states = out_base + 256;
    float* out_ctx    = out_states + 8192 * 256;
    float* out_alpha  = out_ctx + 128 * 256;
    const bool full = (out_size >= total_expected);

    float *pconv, *px, *pgates;
    cudaGetSymbolAddress((void**)&pconv, g_conv);
    cudaGetSymbolAddress((void**)&px, g_x);
    cudaGetSymbolAddress((void**)&pgates, g_gates);

    // 1) fused conv + weighted sum -> g_conv [8192,256]
    conv_kernel<<<Bsz * Ssz, 256>>>(inputs, conv_w, conv_b, pconv);

    // 2) embed + hardtanh -> g_x [8192,256]
    sgemm_nt<true, false><<<dim3(256 / BN, 8192 / BM), 256>>>(
        pconv, embed_w, nullptr, px, 8192, 256, 256);

    // 3) two bidirectional GRU layers
    for (int l = 0; l < 2; l++) {
        const float* WihL = Wih + (size_t)l * 2 * 384 * 256;
        const float* bihL = bih + (size_t)l * 2 * 384;
        const float* WhhL = Whh + (size_t)l * 2 * 384 * 128;
        const float* bhhL = bhh + (size_t)l * 2 * 384;

        sgemm_nt<false, true><<<dim3(768 / BN, 8192 / BM), 256>>>(
            px, WihL, bihL, pgates, 8192, 768, 256);

        float* dst = (l == 0) ? px : (full ? out_states : px);
        gru_scan<<<128, 384>>>(pgates, WhhL, bhhL, dst);
    }

    // 4) epilogue: context / alpha / output softmax
    const float* states_src = full ? out_states : px;
    if (full) {
        epilogue_kernel<<<Bsz, 256>>>(states_src, lin_w, lin_b,
                                      out_out, out_ctx, out_alpha);
    } else {
        epilogue_kernel<<<Bsz, 256>>>(states_src, lin_w, lin_b,
                                      out_out, pconv, pconv + 128 * 256);
    }
}

// round 5
// speedup vs baseline: 1.6869x; 1.6451x over previous
#include <cuda_runtime.h>
#include <cuda_bf16.h>
#include <cstdint>

// ---------------- scratch (static __device__, no allocation) ----------------
__device__ float g_conv[8192 * 256];                          // conv_all
__device__ float g_x[8192 * 256];                             // layer io
__device__ float g_gates[8192 * 768];                         // xg
__device__ __align__(16) __nv_bfloat16 g_aext[8192 * 768];    // A hi/lo ext
__device__ __align__(16) __nv_bfloat16 g_bext[768 * 768];     // B hi/lo ext

#define Bsz 128
#define Ssz 64
#define Psz 32
#define Dsz 256
#define Hsz 128
#define KEXT 768

// packed f32x2 FMA (gru_scan only — measured fastest there)
#define FMA2(acc, a, b) \
    asm("fma.rn.f32x2 %0, %1, %2, %0;" : "+l"(acc) : "l"(a), "l"(b))
__device__ __forceinline__ float pk_lo(unsigned long long p) {
    return __uint_as_float((unsigned)(p & 0xffffffffull));
}
__device__ __forceinline__ float pk_hi(unsigned long long p) {
    return __uint_as_float((unsigned)(p >> 32));
}
__device__ __forceinline__ float fsig(float x) {
    float e = __expf(-x);
    return __fdividef(1.0f, 1.0f + e);
}
__device__ __forceinline__ float ftanh(float x) {
    float ax = fabsf(x);
    float e = __expf(-2.0f * ax);
    float r = __fdividef(1.0f - e, 1.0f + e);
    return copysignf(r, x);
}

// ---------------- baseline-PTX tensor helpers (no sm_103a features) --------
__device__ __forceinline__ void ldmx4(uint32_t* r, uint32_t addr) {
    asm volatile("ldmatrix.sync.aligned.m8n8.x4.shared.b16 {%0,%1,%2,%3}, [%4];"
                 : "=r"(r[0]), "=r"(r[1]), "=r"(r[2]), "=r"(r[3]) : "r"(addr));
}
__device__ __forceinline__ void mma_bf16(float* d, const uint32_t* a,
                                         const uint32_t* b) {
    asm volatile(
        "mma.sync.aligned.m16n8k16.row.col.f32.bf16.bf16.f32 "
        "{%0,%1,%2,%3}, {%4,%5,%6,%7}, {%8,%9}, {%0,%1,%2,%3};"
        : "+f"(d[0]), "+f"(d[1]), "+f"(d[2]), "+f"(d[3])
        : "r"(a[0]), "r"(a[1]), "r"(a[2]), "r"(a[3]), "r"(b[0]), "r"(b[1]));
}
#define CP_ASYNC16(sm, gm) \
    asm volatile("cp.async.cg.shared.global [%0], [%1], 16;" \
                 :: "r"(sm), "l"(gm))
#define CP_COMMIT() asm volatile("cp.async.commit_group;" ::: "memory")
#define CP_WAIT1()  asm volatile("cp.async.wait_group 1;" ::: "memory")
#define CP_WAIT0()  asm volatile("cp.async.wait_group 0;" ::: "memory")

__device__ __forceinline__ uint32_t smem_u32(const void* p) {
    uint32_t a;
    asm("{ .reg .u64 t; cvta.to.shared.u64 t, %1; cvt.u32.u64 %0, t; }"
        : "=r"(a) : "l"(p));
    return a;
}

// =====================================================================
// Kernel 1: fused conv scalar + weighted event sum (HBM streaming)
// =====================================================================
__global__ __launch_bounds__(256)
void conv_kernel(const float* __restrict__ in, const float* __restrict__ conv_w,
                 const float* __restrict__ conv_b, float* __restrict__ out)
{
    __shared__ __align__(16) float tile[Psz * Dsz];
    __shared__ float cw[Dsz];
    __shared__ float sp[Psz];

    const int tid = threadIdx.x;
    const float* src = in + (size_t)blockIdx.x * (Psz * Dsz);

    cw[tid] = conv_w[tid];
    const float4* src4 = (const float4*)src;
    float4* tile4 = (float4*)tile;
#pragma unroll
    for (int i = 0; i < 8; i++)
        tile4[tid + i * 256] = src4[tid + i * 256];
    __syncthreads();

    const int warp = tid >> 5, lane = tid & 31;
#pragma unroll
    for (int r = 0; r < 4; r++) {
        int p = warp * 4 + r;
        float acc = 0.f;
#pragma unroll
        for (int j = 0; j < 8; j++)
            acc += tile[p * Dsz + lane + j * 32] * cw[lane + j * 32];
#pragma unroll
        for (int o = 16; o; o >>= 1)
            acc += __shfl_xor_sync(0xffffffffu, acc, o);
        if (lane == 0) sp[p] = acc + conv_b[0];
    }
    __syncthreads();

    float acc = 0.f;
#pragma unroll
    for (int p = 0; p < Psz; p++)
        acc += sp[p] * tile[p * Dsz + tid];
    out[(size_t)blockIdx.x * Dsz + tid] = acc;
}

// =====================================================================
// Conversion: fp32 [rows,256] -> bf16-extended [rows,768]
// A layout: [hi, lo, hi]   B layout: [hi, hi, lo]
//   => dot(768) = ah*bh + al*bh + ah*bl  (drops al*bl ~4e-6 rel)
// =====================================================================
__global__ __launch_bounds__(256)
void convertA(const float* __restrict__ in, __nv_bfloat16* __restrict__ out)
{
    const int row = blockIdx.x, k = threadIdx.x;
    float x = in[(size_t)row * 256 + k];
    __nv_bfloat16 h = __float2bfloat16(x);
    __nv_bfloat16 l = __float2bfloat16(x - __bfloat162float(h));
    __nv_bfloat16* o = out + (size_t)row * KEXT;
    o[k] = h; o[256 + k] = l; o[512 + k] = h;
}
__global__ __launch_bounds__(256)
void convertB(const float* __restrict__ in, __nv_bfloat16* __restrict__ out)
{
    const int row = blockIdx.x, k = threadIdx.x;
    float x = in[(size_t)row * 256 + k];
    __nv_bfloat16 h = __float2bfloat16(x);
    __nv_bfloat16 l = __float2bfloat16(x - __bfloat162float(h));
    __nv_bfloat16* o = out + (size_t)row * KEXT;
    o[k] = h; o[256 + k] = h; o[512 + k] = l;
}

// =====================================================================
// Kernel 2: mma.sync bf16 GEMM (baseline PTX; tensor pipe via HMMA).
// C[m,n] = sum_k' Aext[m,k']*Bext[n,k']  (+bias) (clip)
// BM=128 BN=64 BK=32(bf16), 256 thr = 8 warps (4 m x 2 n), warp 32x32.
// Double-buffered cp.async; ldmatrix fragments; fp32 accum.
// =====================================================================
#define GBM 128
#define GBN 64
#define LDE 40                     // padded row: 40 bf16 = 80 B
#define ABYTES (128 * LDE * 2)     // 10240
#define BBYTES (64 * LDE * 2)      // 5120

template<bool CLIP, bool BIAS>
__global__ __launch_bounds__(256, 1)
void tgemm_mma(const __nv_bfloat16* __restrict__ Aext,
               const __nv_bfloat16* __restrict__ Bext,
               const float* __restrict__ bias, float* __restrict__ C, int Ntot)
{
    __shared__ __align__(16) uint8_t smem[2 * (ABYTES + BBYTES)];  // 30 KB

    const int tid = threadIdx.x;
    const int wid = tid >> 5, lane = tid & 31;
    const int bm = blockIdx.y * GBM;
    const int bn = blockIdx.x * GBN;

    const uint32_t smA = smem_u32(smem);
    const uint32_t smB = smA + 2 * ABYTES;

    const int warp_m = wid >> 1;          // 0..3
    const int warp_n = wid & 1;           // 0..1

    float acc[2][4][4];
#pragma unroll
    for (int i = 0; i < 2; i++)
#pragma unroll
        for (int j = 0; j < 4; j++)
#pragma unroll
            for (int q = 0; q < 4; q++) acc[i][j][q] = 0.f;

    // per-thread global load coords
    const int arow = tid >> 2, aseg = tid & 3;   // A: 2 iters cover 128 rows
    const int brow = tid >> 2, bseg = tid & 3;   // B: 64 rows x 4 segs = 256

    // ldmatrix per-lane base offsets
    const int lrow = lane & 15;
    const int lcol = (lane >> 4) * 16;           // byte offset

#define LOAD_TILE(step, buf) do {                                              \
    int kt = (step) * 32;                                                      \
    uint32_t a_s = smA + (buf) * ABYTES;                                       \
    uint32_t b_s = smB + (buf) * BBYTES;                                       \
    CP_ASYNC16(a_s + arow * 80 + aseg * 16,                                    \
               Aext + (size_t)(bm + arow) * KEXT + kt + aseg * 8);             \
    CP_ASYNC16(a_s + (arow + 64) * 80 + aseg * 16,                             \
               Aext + (size_t)(bm + arow + 64) * KEXT + kt + aseg * 8);        \
    CP_ASYNC16(b_s + brow * 80 + bseg * 16,                                    \
               Bext + (size_t)(bn + brow) * KEXT + kt + bseg * 8);             \
} while (0)

    LOAD_TILE(0, 0);
    CP_COMMIT();

    for (int s = 0; s < 24; s++) {
        const int cur = s & 1;
        if (s + 1 < 24) {
            LOAD_TILE(s + 1, cur ^ 1);
            CP_COMMIT();
            CP_WAIT1();
        } else {
            CP_WAIT0();
        }
        __syncthreads();

        const uint32_t aBase = smA + cur * ABYTES
                             + (warp_m * 32 + lrow) * 80 + lcol;
        const uint32_t bBase = smB + cur * BBYTES
                             + (warp_n * 32 + lrow) * 80 + lcol;
#pragma unroll
        for (int ks = 0; ks < 2; ks++) {
            uint32_t a0[4], a1[4], bA[4], bB[4];
            ldmx4(a0, aBase + ks * 32);
            ldmx4(a1, aBase + 16 * 80 + ks * 32);
            ldmx4(bA, bBase + ks * 32);            // n 0-15 of warp tile
            ldmx4(bB, bBase + 16 * 80 + ks * 32);  // n 16-31
            uint32_t bf[4][2] = {{bA[0], bA[2]}, {bA[1], bA[3]},
                                 {bB[0], bB[2]}, {bB[1], bB[3]}};
#pragma unroll
            for (int fn = 0; fn < 4; fn++) {
                mma_bf16(acc[0][fn], a0, bf[fn]);
                mma_bf16(acc[1][fn], a1, bf[fn]);
            }
        }
        __syncthreads();
    }
#undef LOAD_TILE

    // epilogue: D frag -> C. lane qr=row, qc=col-pair.
    const int qr = lane >> 2;
    const int qc = (lane & 3) * 2;
#pragma unroll
    for (int fm = 0; fm < 2; fm++) {
#pragma unroll
        for (int fn = 0; fn < 4; fn++) {
            const int m0 = bm + warp_m * 32 + fm * 16 + qr;
            const int n0 = bn + warp_n * 32 + fn * 8 + qc;
            float b0 = 0.f, b1 = 0.f;
            if (BIAS) { b0 = bias[n0]; b1 = bias[n0 + 1]; }
            float v0 = acc[fm][fn][0] + b0;
            float v1 = acc[fm][fn][1] + b1;
            float v2 = acc[fm][fn][2] + b0;
            float v3 = acc[fm][fn][3] + b1;
            if (CLIP) {
                v0 = fminf(1.f, fmaxf(-1.f, v0));
                v1 = fminf(1.f, fmaxf(-1.f, v1));
                v2 = fminf(1.f, fmaxf(-1.f, v2));
                v3 = fminf(1.f, fmaxf(-1.f, v3));
            }
            *(float2*)&C[(size_t)m0 * Ntot + n0]       = make_float2(v0, v1);
            *(float2*)&C[(size_t)(m0 + 8) * Ntot + n0] = make_float2(v2, v3);
        }
    }
}

// =====================================================================
// Kernel 3: GRU scan (round-3 best: FMA2 matvec, latency-bound)
// =====================================================================
__global__ __launch_bounds__(384, 1)
void gru_scan(const float* __restrict__ gates, const float* __restrict__ Whh,
              const float* __restrict__ bhh, float* __restrict__ out)
{
    const int dir = blockIdx.x >> 6;
    const int bpair = blockIdx.x & 63;
    const int b0 = bpair * 2;
    const int g = threadIdx.x;

    const ulonglong2* W2 = (const ulonglong2*)(Whh + (size_t)dir * 384 * 128
                                               + (size_t)g * 128);
    unsigned long long w[64];
#pragma unroll
    for (int i = 0; i < 32; i++) {
        ulonglong2 t = W2[i];
        w[2 * i] = t.x; w[2 * i + 1] = t.y;
    }
    const float bias = bhh[dir * 384 + g];

    __shared__ __align__(16) float h0[Hsz];
    __shared__ __align__(16) float h1[Hsz];
    __shared__ float gh0[384];
    __shared__ float gh1[384];

    if (g < Hsz) { h0[g] = 0.f; h1[g] = 0.f; }
    __syncthreads();

    const int j = g & 127;
    const int isb1 = (g >= 128 && g < 256) ? 1 : 0;
    const int bc = b0 + isb1;

    const ulonglong2* h0v = (const ulonglong2*)h0;
    const ulonglong2* h1v = (const ulonglong2*)h1;

    for (int t_ = 0; t_ < Ssz; t_++) {
        const int t = dir ? (Ssz - 1 - t_) : t_;

        float xr = 0.f, xz = 0.f, xn = 0.f;
        if (g < 256) {
            const float* gb = gates + ((size_t)(bc * Ssz + t)) * 768 + dir * 384;
            xr = gb[j];
            xz = gb[128 + j];
            xn = gb[256 + j];
        }

        unsigned long long acc0 = 0ull, acc1 = 0ull;
#pragma unroll
        for (int i = 0; i < 32; i++) {
            ulonglong2 p = h0v[i];
            ulonglong2 q = h1v[i];
            FMA2(acc0, w[2 * i],     p.x);
            FMA2(acc0, w[2 * i + 1], p.y);
            FMA2(acc1, w[2 * i],     q.x);
            FMA2(acc1, w[2 * i + 1], q.y);
        }
        gh0[g] = pk_lo(acc0) + pk_hi(acc0) + bias;
        gh1[g] = pk_lo(acc1) + pk_hi(acc1) + bias;
        __syncthreads();

        if (g < 256) {
            float* h  = isb1 ? h1 : h0;
            float* gh = isb1 ? gh1 : gh0;
            float r = fsig(xr + gh[j]);
            float z = fsig(xz + gh[128 + j]);
            float n = ftanh(xn + r * gh[256 + j]);
            float hnew = n + z * (h[j] - n);
            h[j] = hnew;
            out[((size_t)(bc * Ssz + t)) * 256 + dir * 128 + j] = hnew;
        }
        __syncthreads();
    }
}

// =====================================================================
// Kernel 4: epilogue (alpha == 1 exactly: softmax over singleton axis)
// =====================================================================
__global__ __launch_bounds__(256)
void epilogue_kernel(const float* __restrict__ states, const float* __restrict__ lin_w,
                     const float* __restrict__ lin_b, float* __restrict__ out_out,
                     float* __restrict__ out_ctx, float* __restrict__ out_alpha)
{
    __shared__ float ctx[256];
    __shared__ float logits[2];
    const int b = blockIdx.x;
    const int tid = threadIdx.x;

    const float* sb = states + (size_t)b * Ssz * 256;
    float acc = 0.f;
#pragma unroll
    for (int s = 0; s < Ssz; s++)
        acc += sb[s * 256 + tid];
    ctx[tid] = acc;
    out_ctx[(size_t)b * 256 + tid] = acc;
    if (tid < Ssz) out_alpha[(size_t)b * Ssz + tid] = 1.0f;
    __syncthreads();

    if (tid < 64) {
        const int o = tid >> 5, lane = tid & 31;
        float p = 0.f;
#pragma unroll
        for (int k = 0; k < 8; k++)
            p += ctx[lane + k * 32] * lin_w[o * 256 + lane + k * 32];
#pragma unroll
        for (int off = 16; off; off >>= 1)
            p += __shfl_xor_sync(0xffffffffu, p, off);
        if (lane == 0) logits[o] = p + lin_b[o];
    }
    __syncthreads();
    if (tid == 0) {
        float l0 = logits[0], l1 = logits[1];
        float m = fmaxf(l0, l1);
        float e0 = expf(l0 - m), e1 = expf(l1 - m);
        float inv = 1.0f / (e0 + e1);
        out_out[b * 2 + 0] = e0 * inv;
        out_out[b * 2 + 1] = e1 * inv;
    }
}

// =====================================================================
// launcher
// =====================================================================
extern "C" void kernel_launch(void* const* d_in, const int* in_sizes, int n_in,
                              void* d_out, int out_size)
{
    const float* inputs  = (const float*)d_in[0];
    const float* conv_w  = (const float*)d_in[1];
    const float* conv_b  = (const float*)d_in[2];
    const float* embed_w = (const float*)d_in[3];
    const float* Wih     = (const float*)d_in[4];
    const float* Whh     = (const float*)d_in[5];
    const float* bih     = (const float*)d_in[6];
    const float* bhh     = (const float*)d_in[7];
    const float* lin_w   = (const float*)d_in[9];
    const float* lin_b   = (const float*)d_in[10];

    float* out_base = (float*)d_out;
    const int total_expected = 256 + 8192 * 256 + 128 * 256 + 128 * 64;
    float* out_out    = out_base;
    float* out_states = out_base + 256;
    float* out_ctx    = out_states + 8192 * 256;
    float* out_alpha  = out_ctx + 128 * 256;
    const bool full = (out_size >= total_expected);

    float *pconv, *px, *pgates;
    __nv_bfloat16 *paext, *pbext;
    cudaGetSymbolAddress((void**)&pconv, g_conv);
    cudaGetSymbolAddress((void**)&px, g_x);
    cudaGetSymbolAddress((void**)&pgates, g_gates);
    cudaGetSymbolAddress((void**)&paext, g_aext);
    cudaGetSymbolAddress((void**)&pbext, g_bext);

    // 1) fused conv + weighted sum -> g_conv [8192,256]
    conv_kernel<<<Bsz * Ssz, 256>>>(inputs, conv_w, conv_b, pconv);

    // 2) embed + hardtanh via tensor GEMM (N=256)
    convertA<<<8192, 256>>>(pconv, paext);
    convertB<<<256, 256>>>(embed_w, pbext);
    tgemm_mma<true, false><<<dim3(256 / GBN, 8192 / GBM), 256>>>(
        paext, pbext, nullptr, px, 256);

    // 3) two bidirectional GRU layers
    for (int l = 0; l < 2; l++) {
        const float* WihL = Wih + (size_t)l * 2 * 384 * 256;
        const float* bihL = bih + (size_t)l * 2 * 384;
        const float* WhhL = Whh + (size_t)l * 2 * 384 * 128;
        const float* bhhL = bhh + (size_t)l * 2 * 384;

        convertA<<<8192, 256>>>(px, paext);
        convertB<<<768, 256>>>(WihL, pbext);
        tgemm_mma<false, true><<<dim3(768 / GBN, 8192 / GBM), 256>>>(
            paext, pbext, bihL, pgates, 768);

        float* dst = (l == 0) ? px : (full ? out_states : px);
        gru_scan<<<128, 384>>>(pgates, WhhL, bhhL, dst);
    }

    // 4) epilogue
    const float* states_src = full ? out_states : px;
    if (full) {
        epilogue_kernel<<<Bsz, 256>>>(states_src, lin_w, lin_b,
                                      out_out, out_ctx, out_alpha);
    } else {
        epilogue_kernel<<<Bsz, 256>>>(states_src, lin_w, lin_b,
                                      out_out, pconv, pconv + 128 * 256);
    }
}

// round 6
// speedup vs baseline: 1.7856x; 1.0585x over previous
#include <cuda_runtime.h>
#include <cuda_bf16.h>
#include <cstdint>

// ---------------- scratch (static __device__, no allocation) ----------------
__device__ float g_x[8192 * 256];                              // fallback only
__device__ float g_gates[8192 * 768];                          // xg
__device__ __align__(16) __nv_bfloat16 g_aext[8192 * 768];     // A ext buf 1
__device__ __align__(16) __nv_bfloat16 g_aext2[8192 * 768];    // A ext buf 2
__device__ __align__(16) __nv_bfloat16 g_bext[768 * 768];      // B ext

#define Bsz 128
#define Ssz 64
#define Psz 32
#define Dsz 256
#define Hsz 128
#define KEXT 768

// packed f32x2 FMA (gru_scan only — measured fastest there)
#define FMA2(acc, a, b) \
    asm("fma.rn.f32x2 %0, %1, %2, %0;" : "+l"(acc) : "l"(a), "l"(b))
__device__ __forceinline__ float pk_lo(unsigned long long p) {
    return __uint_as_float((unsigned)(p & 0xffffffffull));
}
__device__ __forceinline__ float pk_hi(unsigned long long p) {
    return __uint_as_float((unsigned)(p >> 32));
}
__device__ __forceinline__ float fsig(float x) {
    float e = __expf(-x);
    return __fdividef(1.0f, 1.0f + e);
}
__device__ __forceinline__ float ftanh(float x) {
    float ax = fabsf(x);
    float e = __expf(-2.0f * ax);
    float r = __fdividef(1.0f - e, 1.0f + e);
    return copysignf(r, x);
}

// hi/lo bf16 split store: [hi | lo | hi-dup] at +0, +256, +512 (A layout)
__device__ __forceinline__ void store_ext2(__nv_bfloat16* base, float v0, float v1) {
    __nv_bfloat16 h0 = __float2bfloat16(v0), h1 = __float2bfloat16(v1);
    __nv_bfloat16 l0 = __float2bfloat16(v0 - __bfloat162float(h0));
    __nv_bfloat16 l1 = __float2bfloat16(v1 - __bfloat162float(h1));
    __nv_bfloat162 hh; hh.x = h0; hh.y = h1;
    __nv_bfloat162 ll; ll.x = l0; ll.y = l1;
    *(__nv_bfloat162*)(base)       = hh;
    *(__nv_bfloat162*)(base + 256) = ll;
    *(__nv_bfloat162*)(base + 512) = hh;
}

// ---------------- baseline-PTX tensor helpers ----------------
__device__ __forceinline__ void ldmx4(uint32_t* r, uint32_t addr) {
    asm volatile("ldmatrix.sync.aligned.m8n8.x4.shared.b16 {%0,%1,%2,%3}, [%4];"
                 : "=r"(r[0]), "=r"(r[1]), "=r"(r[2]), "=r"(r[3]) : "r"(addr));
}
__device__ __forceinline__ void mma_bf16(float* d, const uint32_t* a,
                                         const uint32_t* b) {
    asm volatile(
        "mma.sync.aligned.m16n8k16.row.col.f32.bf16.bf16.f32 "
        "{%0,%1,%2,%3}, {%4,%5,%6,%7}, {%8,%9}, {%0,%1,%2,%3};"
        : "+f"(d[0]), "+f"(d[1]), "+f"(d[2]), "+f"(d[3])
        : "r"(a[0]), "r"(a[1]), "r"(a[2]), "r"(a[3]), "r"(b[0]), "r"(b[1]));
}
#define CP_ASYNC16(sm, gm) \
    asm volatile("cp.async.cg.shared.global [%0], [%1], 16;" \
                 :: "r"(sm), "l"(gm))
#define CP_COMMIT() asm volatile("cp.async.commit_group;" ::: "memory")
#define CP_WAIT1()  asm volatile("cp.async.wait_group 1;" ::: "memory")
#define CP_WAIT0()  asm volatile("cp.async.wait_group 0;" ::: "memory")

__device__ __forceinline__ uint32_t smem_u32(const void* p) {
    uint32_t a;
    asm("{ .reg .u64 t; cvta.to.shared.u64 t, %1; cvt.u32.u64 %0, t; }"
        : "=r"(a) : "l"(p));
    return a;
}

// =====================================================================
// Kernel 1: fused conv + weighted event sum -> writes A_ext directly
// =====================================================================
__global__ __launch_bounds__(256)
void conv_kernel(const float* __restrict__ in, const float* __restrict__ conv_w,
                 const float* __restrict__ conv_b, __nv_bfloat16* __restrict__ aext)
{
    __shared__ __align__(16) float tile[Psz * Dsz];
    __shared__ float cw[Dsz];
    __shared__ float sp[Psz];

    const int tid = threadIdx.x;
    const float* src = in + (size_t)blockIdx.x * (Psz * Dsz);

    cw[tid] = conv_w[tid];
    const float4* src4 = (const float4*)src;
    float4* tile4 = (float4*)tile;
#pragma unroll
    for (int i = 0; i < 8; i++)
        tile4[tid + i * 256] = src4[tid + i * 256];
    __syncthreads();

    const int warp = tid >> 5, lane = tid & 31;
#pragma unroll
    for (int r = 0; r < 4; r++) {
        int p = warp * 4 + r;
        float acc = 0.f;
#pragma unroll
        for (int j = 0; j < 8; j++)
            acc += tile[p * Dsz + lane + j * 32] * cw[lane + j * 32];
#pragma unroll
        for (int o = 16; o; o >>= 1)
            acc += __shfl_xor_sync(0xffffffffu, acc, o);
        if (lane == 0) sp[p] = acc + conv_b[0];
    }
    __syncthreads();

    float acc = 0.f;
#pragma unroll
    for (int p = 0; p < Psz; p++)
        acc += sp[p] * tile[p * Dsz + tid];

    __nv_bfloat16 h = __float2bfloat16(acc);
    __nv_bfloat16 l = __float2bfloat16(acc - __bfloat162float(h));
    __nv_bfloat16* o = aext + (size_t)blockIdx.x * KEXT;
    o[tid] = h; o[256 + tid] = l; o[512 + tid] = h;
}

// =====================================================================
// B conversion: fp32 [rows,256] -> bf16 ext [rows,768] = [hi, hi, lo]
// =====================================================================
__global__ __launch_bounds__(256)
void convertB(const float* __restrict__ in, __nv_bfloat16* __restrict__ out)
{
    const int row = blockIdx.x, k = threadIdx.x;
    float x = in[(size_t)row * 256 + k];
    __nv_bfloat16 h = __float2bfloat16(x);
    __nv_bfloat16 l = __float2bfloat16(x - __bfloat162float(h));
    __nv_bfloat16* o = out + (size_t)row * KEXT;
    o[k] = h; o[256 + k] = h; o[512 + k] = l;
}

// =====================================================================
// Kernel 2: mma.sync bf16 GEMM, 3-stage cp.async, one sync/step.
// C = Aext @ Bext^T over K'=768 (24 steps of BK=32).
// BM=128 BN=64; 8 warps (4m x 2n), warp tile 32x32; fp32 accum.
// AEXT=0: C fp32 (+bias). AEXT=1: clip + hi/lo split -> bf16 ext rows.
// =====================================================================
#define GBM 128
#define GBN 64
#define LDE 40                       // padded row: 40 bf16 = 80 B
#define ABYTES (128 * LDE * 2)       // 10240
#define BBYTES (64 * LDE * 2)        // 5120
#define STAGEB (ABYTES + BBYTES)     // 15360 ; x3 = 46080 < 48K
#define NSTEP 24

template<bool AEXT, bool BIAS>
__global__ __launch_bounds__(256)
void tgemm_mma(const __nv_bfloat16* __restrict__ Aext,
               const __nv_bfloat16* __restrict__ Bext,
               const float* __restrict__ bias, float* __restrict__ Cf,
               __nv_bfloat16* __restrict__ Ce, int Ntot)
{
    __shared__ __align__(16) uint8_t smem[3 * STAGEB];

    const int tid = threadIdx.x;
    const int wid = tid >> 5, lane = tid & 31;
    const int bm = blockIdx.y * GBM;
    const int bn = blockIdx.x * GBN;

    const uint32_t smBase = smem_u32(smem);

    const int warp_m = wid >> 1;
    const int warp_n = wid & 1;

    float acc[2][4][4];
#pragma unroll
    for (int i = 0; i < 2; i++)
#pragma unroll
        for (int j = 0; j < 4; j++)
#pragma unroll
            for (int q = 0; q < 4; q++) acc[i][j][q] = 0.f;

    const int arow = tid >> 2, aseg = tid & 3;
    const int lrow = lane & 15;
    const int lcol = (lane >> 4) * 16;

#define LOAD_TILE(step, buf) do {                                              \
    int kt = (step) * 32;                                                      \
    uint32_t a_s = smBase + (buf) * STAGEB;                                    \
    uint32_t b_s = a_s + ABYTES;                                               \
    CP_ASYNC16(a_s + arow * 80 + aseg * 16,                                    \
               Aext + (size_t)(bm + arow) * KEXT + kt + aseg * 8);             \
    CP_ASYNC16(a_s + (arow + 64) * 80 + aseg * 16,                             \
               Aext + (size_t)(bm + arow + 64) * KEXT + kt + aseg * 8);        \
    CP_ASYNC16(b_s + arow * 80 + aseg * 16,                                    \
               Bext + (size_t)(bn + arow) * KEXT + kt + aseg * 8);             \
} while (0)

    LOAD_TILE(0, 0); CP_COMMIT();
    LOAD_TILE(1, 1); CP_COMMIT();

    int buf = 0;
    for (int s = 0; s < NSTEP; s++) {
        if (s == NSTEP - 1) { CP_WAIT0(); } else { CP_WAIT1(); }
        __syncthreads();

        const uint32_t aBase = smBase + buf * STAGEB
                             + (warp_m * 32 + lrow) * 80 + lcol;
        const uint32_t bBase = smBase + buf * STAGEB + ABYTES
                             + (warp_n * 32 + lrow) * 80 + lcol;
#pragma unroll
        for (int ks = 0; ks < 2; ks++) {
            uint32_t a0[4], a1[4], bA[4], bB[4];
            ldmx4(a0, aBase + ks * 32);
            ldmx4(a1, aBase + 16 * 80 + ks * 32);
            ldmx4(bA, bBase + ks * 32);
            ldmx4(bB, bBase + 16 * 80 + ks * 32);
            uint32_t bf[4][2] = {{bA[0], bA[2]}, {bA[1], bA[3]},
                                 {bB[0], bB[2]}, {bB[1], bB[3]}};
#pragma unroll
            for (int fn = 0; fn < 4; fn++) {
                mma_bf16(acc[0][fn], a0, bf[fn]);
                mma_bf16(acc[1][fn], a1, bf[fn]);
            }
        }
        // issue stage s+2 AFTER this step's sync: all warps have finished
        // reading buffer (s+2)%3 (they read it in step s-1).
        if (s + 2 < NSTEP) { LOAD_TILE(s + 2, (s + 2) % 3); CP_COMMIT(); }
        buf = (buf + 1 == 3) ? 0 : buf + 1;
    }
#undef LOAD_TILE

    const int qr = lane >> 2;
    const int qc = (lane & 3) * 2;
#pragma unroll
    for (int fm = 0; fm < 2; fm++) {
#pragma unroll
        for (int fn = 0; fn < 4; fn++) {
            const int m0 = bm + warp_m * 32 + fm * 16 + qr;
            const int n0 = bn + warp_n * 32 + fn * 8 + qc;
            float b0 = 0.f, b1 = 0.f;
            if (BIAS) { b0 = bias[n0]; b1 = bias[n0 + 1]; }
            float v0 = acc[fm][fn][0] + b0;
            float v1 = acc[fm][fn][1] + b1;
            float v2 = acc[fm][fn][2] + b0;
            float v3 = acc[fm][fn][3] + b1;
            if (AEXT) {
                v0 = fminf(1.f, fmaxf(-1.f, v0));
                v1 = fminf(1.f, fmaxf(-1.f, v1));
                v2 = fminf(1.f, fmaxf(-1.f, v2));
                v3 = fminf(1.f, fmaxf(-1.f, v3));
                store_ext2(Ce + (size_t)m0 * KEXT + n0, v0, v1);
                store_ext2(Ce + (size_t)(m0 + 8) * KEXT + n0, v2, v3);
            } else {
                *(float2*)&Cf[(size_t)m0 * Ntot + n0]       = make_float2(v0, v1);
                *(float2*)&Cf[(size_t)(m0 + 8) * Ntot + n0] = make_float2(v2, v3);
            }
        }
    }
}

// =====================================================================
// Kernel 3: GRU scan; 4-way split accumulator chains (latency fix).
// EXT=1: write bf16 hi/lo ext rows (feeds next layer's GEMM).
// EXT=0: write fp32 states.
// =====================================================================
template<bool EXT>
__global__ __launch_bounds__(384, 1)
void gru_scan(const float* __restrict__ gates, const float* __restrict__ Whh,
              const float* __restrict__ bhh, float* __restrict__ outF,
              __nv_bfloat16* __restrict__ outE)
{
    const int dir = blockIdx.x >> 6;
    const int bpair = blockIdx.x & 63;
    const int b0 = bpair * 2;
    const int g = threadIdx.x;

    const ulonglong2* W2 = (const ulonglong2*)(Whh + (size_t)dir * 384 * 128
                                               + (size_t)g * 128);
    unsigned long long w[64];
#pragma unroll
    for (int i = 0; i < 32; i++) {
        ulonglong2 t = W2[i];
        w[2 * i] = t.x; w[2 * i + 1] = t.y;
    }
    const float bias = bhh[dir * 384 + g];

    __shared__ __align__(16) float h0[Hsz];
    __shared__ __align__(16) float h1[Hsz];
    __shared__ float gh0[384];
    __shared__ float gh1[384];

    if (g < Hsz) { h0[g] = 0.f; h1[g] = 0.f; }
    __syncthreads();

    const int j = g & 127;
    const int isb1 = (g >= 128 && g < 256) ? 1 : 0;
    const int bc = b0 + isb1;

    const ulonglong2* h0v = (const ulonglong2*)h0;
    const ulonglong2* h1v = (const ulonglong2*)h1;

    for (int t_ = 0; t_ < Ssz; t_++) {
        const int t = dir ? (Ssz - 1 - t_) : t_;

        float xr = 0.f, xz = 0.f, xn = 0.f;
        if (g < 256) {
            const float* gb = gates + ((size_t)(bc * Ssz + t)) * 768 + dir * 384;
            xr = gb[j];
            xz = gb[128 + j];
            xn = gb[256 + j];
        }

        // 4 independent accumulation chains (2 per batch) — 32-deep each
        unsigned long long a0a = 0ull, a0b = 0ull, a1a = 0ull, a1b = 0ull;
#pragma unroll
        for (int i = 0; i < 16; i++) {
            ulonglong2 p  = h0v[i];
            ulonglong2 q  = h1v[i];
            ulonglong2 p2 = h0v[i + 16];
            ulonglong2 q2 = h1v[i + 16];
            FMA2(a0a, w[2 * i],          p.x);
            FMA2(a0a, w[2 * i + 1],      p.y);
            FMA2(a1a, w[2 * i],          q.x);
            FMA2(a1a, w[2 * i + 1],      q.y);
            FMA2(a0b, w[2 * (i + 16)],     p2.x);
            FMA2(a0b, w[2 * (i + 16) + 1], p2.y);
            FMA2(a1b, w[2 * (i + 16)],     q2.x);
            FMA2(a1b, w[2 * (i + 16) + 1], q2.y);
        }
        gh0[g] = (pk_lo(a0a) + pk_hi(a0a)) + (pk_lo(a0b) + pk_hi(a0b)) + bias;
        gh1[g] = (pk_lo(a1a) + pk_hi(a1a)) + (pk_lo(a1b) + pk_hi(a1b)) + bias;
        __syncthreads();

        if (g < 256) {
            float* h  = isb1 ? h1 : h0;
            float* gh = isb1 ? gh1 : gh0;
            float r = fsig(xr + gh[j]);
            float z = fsig(xz + gh[128 + j]);
            float n = ftanh(xn + r * gh[256 + j]);
            float hnew = n + z * (h[j] - n);
            h[j] = hnew;
            if (EXT) {
                __nv_bfloat16 hh = __float2bfloat16(hnew);
                __nv_bfloat16 ll = __float2bfloat16(hnew - __bfloat162float(hh));
                __nv_bfloat16* o = outE + ((size_t)(bc * Ssz + t)) * KEXT
                                 + dir * 128 + j;
                o[0] = hh; o[256] = ll; o[512] = hh;
            } else {
                outF[((size_t)(bc * Ssz + t)) * 256 + dir * 128 + j] = hnew;
            }
        }
        __syncthreads();
    }
}

// =====================================================================
// Kernel 4: epilogue (alpha == 1 exactly: softmax over singleton axis)
// =====================================================================
__global__ __launch_bounds__(256)
void epilogue_kernel(const float* __restrict__ states, const float* __restrict__ lin_w,
                     const float* __restrict__ lin_b, float* __restrict__ out_out,
                     float* __restrict__ out_ctx, float* __restrict__ out_alpha)
{
    __shared__ float ctx[256];
    __shared__ float logits[2];
    const int b = blockIdx.x;
    const int tid = threadIdx.x;

    const float* sb = states + (size_t)b * Ssz * 256;
    float acc = 0.f;
#pragma unroll
    for (int s = 0; s < Ssz; s++)
        acc += sb[s * 256 + tid];
    ctx[tid] = acc;
    out_ctx[(size_t)b * 256 + tid] = acc;
    if (tid < Ssz) out_alpha[(size_t)b * Ssz + tid] = 1.0f;
    __syncthreads();

    if (tid < 64) {
        const int o = tid >> 5, lane = tid & 31;
        float p = 0.f;
#pragma unroll
        for (int k = 0; k < 8; k++)
            p += ctx[lane + k * 32] * lin_w[o * 256 + lane + k * 32];
#pragma unroll
        for (int off = 16; off; off >>= 1)
            p += __shfl_xor_sync(0xffffffffu, p, off);
        if (lane == 0) logits[o] = p + lin_b[o];
    }
    __syncthreads();
    if (tid == 0) {
        float l0 = logits[0], l1 = logits[1];
        float m = fmaxf(l0, l1);
        float e0 = expf(l0 - m), e1 = expf(l1 - m);
        float inv = 1.0f / (e0 + e1);
        out_out[b * 2 + 0] = e0 * inv;
        out_out[b * 2 + 1] = e1 * inv;
    }
}

// =====================================================================
// launcher
// =====================================================================
extern "C" void kernel_launch(void* const* d_in, const int* in_sizes, int n_in,
                              void* d_out, int out_size)
{
    const float* inputs  = (const float*)d_in[0];
    const float* conv_w  = (const float*)d_in[1];
    const float* conv_b  = (const float*)d_in[2];
    const float* embed_w = (const float*)d_in[3];
    const float* Wih     = (const float*)d_in[4];
    const float* Whh     = (const float*)d_in[5];
    const float* bih     = (const float*)d_in[6];
    const float* bhh     = (const float*)d_in[7];
    const float* lin_w   = (const float*)d_in[9];
    const float* lin_b   = (const float*)d_in[10];

    float* out_base = (float*)d_out;
    const int total_expected = 256 + 8192 * 256 + 128 * 256 + 128 * 64;
    float* out_out    = out_base;
    float* out_states = out_base + 256;
    float* out_ctx    = out_states + 8192 * 256;
    float* out_alpha  = out_ctx + 128 * 256;
    const bool full = (out_size >= total_expected);

    float *px, *pgates;
    __nv_bfloat16 *paext, *paext2, *pbext;
    cudaGetSymbolAddress((void**)&px, g_x);
    cudaGetSymbolAddress((void**)&pgates, g_gates);
    cudaGetSymbolAddress((void**)&paext, g_aext);
    cudaGetSymbolAddress((void**)&paext2, g_aext2);
    cudaGetSymbolAddress((void**)&pbext, g_bext);

    // 1) conv + weighted sum -> A_ext (for embed GEMM)
    conv_kernel<<<Bsz * Ssz, 256>>>(inputs, conv_w, conv_b, paext);

    // 2) embed + hardtanh, epilogue writes A_ext2 (input to layer-0 gates)
    convertB<<<256, 256>>>(embed_w, pbext);
    tgemm_mma<true, false><<<dim3(256 / GBN, 8192 / GBM), 256>>>(
        paext, pbext, nullptr, nullptr, paext2, 256);

    // 3) layer 0: gates GEMM -> gru (gru writes A_ext for layer 1)
    convertB<<<768, 256>>>(Wih, pbext);
    tgemm_mma<false, true><<<dim3(768 / GBN, 8192 / GBM), 256>>>(
        paext2, pbext, bih, pgates, nullptr, 768);
    gru_scan<true><<<128, 384>>>(pgates, Whh, bhh, nullptr, paext);

    // 4) layer 1: gates GEMM -> gru (writes fp32 states)
    convertB<<<768, 256>>>(Wih + (size_t)2 * 384 * 256, pbext);
    tgemm_mma<false, true><<<dim3(768 / GBN, 8192 / GBM), 256>>>(
        paext, pbext, bih + 2 * 384, pgates, nullptr, 768);
    float* states_dst = full ? out_states : px;
    gru_scan<false><<<128, 384>>>(pgates, Whh + (size_t)2 * 384 * 128,
                                  bhh + 2 * 384, states_dst, nullptr);

    // 5) epilogue
    if (full) {
        epilogue_kernel<<<Bsz, 256>>>(states_dst, lin_w, lin_b,
                                      out_out, out_ctx, out_alpha);
    } else {
        epilogue_kernel<<<Bsz, 256>>>(states_dst, lin_w, lin_b,
                                      out_out, px, px + 128 * 256);
    }
}